// round 11
// baseline (speedup 1.0000x reference)
#include <cuda_runtime.h>

// FeedForwardAttention — algebraically reduced, persistent kernel with
// read/write phase overlap.
//   attns[b,q,:] = softmax_k(u . key[b,k]),  u = Wk^T fck_w
//   out[b,q,:]   = Wv @ (sum_k e_k value[b,k,:]) / (sum_k e_k) + bv
// Half A = batches 0-3 (128 tiles x 64 rows), half B = batches 4-7
// (64 tiles x 128 rows). Stage 2 overlaps half-B read with half-A write.

#define BB 8
#define LL 2048
#define CC 1024
#define GRID 148
#define TPB 512
#define NTILE 192
#define HALF4 2097152            // float4s per half of output

__device__ float g_upart[128 * CC];
__device__ float g_u[CC];
__device__ float g_vpart[NTILE * CC];
__device__ float g_eblk[NTILE];
__device__ float g_vbar[BB * CC];
__device__ float g_outs[BB * CC];
__device__ unsigned g_slot[8 * 32];   // spread arrival counters (padded)
__device__ unsigned g_gen2;           // monotonic release counter

// Monotonic barrier: arrivals spread over 8 counters (19/19/19/19/18/18/18/18
// blocks per slot), block 0 polls slots and releases via g_gen2. No resets:
// counters and gen advance in lockstep, so targets derive from the entry
// snapshot m0 (counter[s] == m * ns exactly when gen == m).
__device__ __forceinline__ void grid_barrier(int bk, unsigned m0, unsigned k) {
    __syncthreads();
    int t = threadIdx.x;
    if (t == 0) {
        __threadfence();
        atomicAdd(&g_slot[(bk & 7) * 32], 1u);
    }
    if (bk == 0) {
        if (t < 8) {
            unsigned ns = (t < 4) ? 19u : 18u;
            unsigned target = (m0 + k) * ns;
            while ((int)(*(volatile unsigned*)&g_slot[t * 32] - target) < 0) { }
        }
        __syncthreads();
        if (t == 0) { __threadfence(); *(volatile unsigned*)&g_gen2 = m0 + k; }
    } else {
        if (t == 0) {
            while ((int)(*(volatile unsigned*)&g_gen2 - (m0 + k)) < 0) { }
            __threadfence();
        }
        __syncthreads();
    }
}

// One P1 tile: warp-local dot+exp+value accumulate (round-7 proven form).
template <int NIT>
__device__ __forceinline__ void p1_tile(
    const float4* __restrict__ key4, const float4* __restrict__ value4,
    int row0, int tile, const float4* su4, float4 (*sbuf)[CC / 4], float* sew)
{
    const int t = threadIdx.x, w = t >> 5, lane = t & 31;
    float4 acc[8];
#pragma unroll
    for (int i = 0; i < 8; ++i) acc[i] = make_float4(0.f, 0.f, 0.f, 0.f);
    float e_acc = 0.f;

#pragma unroll 2
    for (int it = 0; it < NIT; ++it) {
        const int row = row0 + it * 16 + w;
        const float4* kr = key4 + (size_t)row * 256;
        const float4* vr = value4 + (size_t)row * 256;
        float4 kv[8], vv[8];
#pragma unroll
        for (int i = 0; i < 8; ++i) kv[i] = kr[lane + i * 32];
#pragma unroll
        for (int i = 0; i < 8; ++i) vv[i] = vr[lane + i * 32];
        float d = 0.f;
#pragma unroll
        for (int i = 0; i < 8; ++i) {
            float4 uv = su4[lane + i * 32];
            d += kv[i].x * uv.x + kv[i].y * uv.y + kv[i].z * uv.z + kv[i].w * uv.w;
        }
#pragma unroll
        for (int o = 16; o; o >>= 1) d += __shfl_xor_sync(0xFFFFFFFFu, d, o);
        const float e = __expf(d);
        e_acc += e;
#pragma unroll
        for (int i = 0; i < 8; ++i) {
            acc[i].x += e * vv[i].x; acc[i].y += e * vv[i].y;
            acc[i].z += e * vv[i].z; acc[i].w += e * vv[i].w;
        }
    }

    // block reduce: 16 warp partials -> 8 bufs -> 1
    if (w < 8) {
#pragma unroll
        for (int i = 0; i < 8; ++i) sbuf[w][lane + i * 32] = acc[i];
    }
    if (lane == 0) sew[w] = e_acc;
    __syncthreads();
    if (w >= 8) {
        int bf = w - 8;
#pragma unroll
        for (int i = 0; i < 8; ++i) {
            float4 c = sbuf[bf][lane + i * 32];
            c.x += acc[i].x; c.y += acc[i].y; c.z += acc[i].z; c.w += acc[i].w;
            sbuf[bf][lane + i * 32] = c;
        }
    }
    __syncthreads();
    if (t < 256) {
        float4 s = make_float4(0.f, 0.f, 0.f, 0.f);
#pragma unroll
        for (int j = 0; j < 8; ++j) {
            float4 c = sbuf[j][t];
            s.x += c.x; s.y += c.y; s.z += c.z; s.w += c.w;
        }
        ((float4*)g_vpart)[tile * 256 + t] = s;
    } else if (w == 8) {
        float s = (lane < 16) ? sew[lane] : 0.f;
#pragma unroll
        for (int o = 16; o; o >>= 1) s += __shfl_xor_sync(0xFFFFFFFFu, s, o);
        if (lane == 0) g_eblk[tile] = s;
    }
}

// Broadcast one half of the output. Grid stride is a multiple of 256 float4s,
// so each thread's column (d4) is fixed: cache the 4 per-batch values in
// registers and emit a pure store stream.
__device__ __forceinline__ void p4_write(
    float4* __restrict__ out, int nblk, int bkloc, int b0, int base4)
{
    const int i0 = bkloc * TPB + threadIdx.x;
    const int d4 = i0 & 255;
    const float4* os = (const float4*)g_outs;
    const float4 r0 = os[(b0 + 0) * 256 + d4];
    const float4 r1 = os[(b0 + 1) * 256 + d4];
    const float4 r2 = os[(b0 + 2) * 256 + d4];
    const float4 r3 = os[(b0 + 3) * 256 + d4];
    const int stride = nblk * TPB;
    for (int i = i0; i < HALF4; i += stride) {
        int b = i >> 19;                  // local batch 0..3
        float4 r = (b == 0) ? r0 : (b == 1) ? r1 : (b == 2) ? r2 : r3;
        out[base4 + i] = r;
    }
}

__global__ void __launch_bounds__(TPB, 1) k_fused(
    const float* __restrict__ key, const float* __restrict__ value,
    const float* __restrict__ Wk, const float* __restrict__ Wv,
    const float* __restrict__ bv, const float* __restrict__ fckw,
    float4* __restrict__ out)
{
    __shared__ float4 su4[CC / 4];
    __shared__ float4 sbuf[8][CC / 4];
    __shared__ float  sew[16];
    __shared__ float  s_scale;

    const int bk = blockIdx.x, t = threadIdx.x;
    const int w = t >> 5, lane = t & 31;
    const float4* key4 = (const float4*)key;
    const float4* value4 = (const float4*)value;

    // Entry snapshot; race-free: g_gen2 only advances after every block has
    // arrived at barrier 1, which happens after this read in program order.
    const unsigned m0 = *(volatile unsigned*)&g_gen2;

    // ---- P0: u partials (128 blocks x 8 o-rows) ---------------------------
    if (bk < 128) {
        int o0 = bk * 8;
        float a0 = 0.f, a1 = 0.f;
#pragma unroll
        for (int o = 0; o < 8; ++o) {
            float f = fckw[o0 + o];
            const float* wr = Wk + (size_t)(o0 + o) * CC;
            a0 += f * wr[t];
            a1 += f * wr[t + 512];
        }
        g_upart[bk * CC + t]       = a0;
        g_upart[bk * CC + t + 512] = a1;
    }
    grid_barrier(bk, m0, 1);

    // ---- P0b: u reduce (2 blocks x 512 cols) ------------------------------
    if (bk < 2) {
        int c = bk * 512 + t;
        float acc = 0.f;
#pragma unroll
        for (int j = 0; j < 128; ++j) acc += g_upart[j * CC + c];
        g_u[c] = acc;
    }
    grid_barrier(bk, m0, 2);

    // stage u into smem (all blocks; used by P1a and P1b)
    if (t < 256) su4[t] = ((const float4*)g_u)[t];
    __syncthreads();

    // ---- P1a: half A, 128 tiles x 64 rows (batches 0-3) -------------------
    if (bk < 128)
        p1_tile<4>(key4, value4, bk * 64, bk, su4, sbuf, sew);
    grid_barrier(bk, m0, 3);

    // ---- P2a: vbar for batches 0-3 (8 blocks) -----------------------------
    if (bk < 8) {
        int b = bk >> 1;
        int tile0 = b * 32;
        int c = (bk & 1) * 512 + t;
        if (t == 0) {
            float es = 0.f;
#pragma unroll
            for (int j = 0; j < 32; ++j) es += g_eblk[tile0 + j];
            s_scale = 1.f / es;
        }
        float acc = 0.f;
#pragma unroll
        for (int j = 0; j < 32; ++j)
            acc += g_vpart[(size_t)(tile0 + j) * CC + c];
        __syncthreads();
        g_vbar[b * CC + c] = acc * s_scale;
    }
    grid_barrier(bk, m0, 4);

    // ---- P3a: outs for batches 0-3 (64 blocks x 16 d) ---------------------
    if (bk < 64) {
        int d = bk * 16 + w;
        const float4* wp = (const float4*)(Wv + (size_t)d * CC);
        const float4* vb = (const float4*)g_vbar;
        float acc[4] = {0.f, 0.f, 0.f, 0.f};
#pragma unroll
        for (int i = 0; i < 8; ++i) {
            int idx = lane + i * 32;
            float4 wv = wp[idx];
#pragma unroll
            for (int b = 0; b < 4; ++b) {
                float4 v = vb[b * 256 + idx];
                acc[b] += wv.x * v.x + wv.y * v.y + wv.z * v.z + wv.w * v.w;
            }
        }
#pragma unroll
        for (int b = 0; b < 4; ++b)
#pragma unroll
            for (int o = 16; o; o >>= 1)
                acc[b] += __shfl_xor_sync(0xFFFFFFFFu, acc[b], o);
        if (lane == 0) {
            float bias = bv[d];
#pragma unroll
            for (int b = 0; b < 4; ++b) g_outs[b * CC + d] = acc[b] + bias;
        }
    }
    grid_barrier(bk, m0, 5);

    // ---- Stage 2: overlap half-B read with half-A write -------------------
    if (bk >= 84) {
        int tl = bk - 84;                        // 0..63
        p1_tile<8>(key4, value4, 8192 + tl * 128, 128 + tl, su4, sbuf, sew);
    } else {
        p4_write(out, 84, bk, 0, 0);             // write batches 0-3 (32MB)
    }
    grid_barrier(bk, m0, 6);

    // ---- P2b: vbar for batches 4-7 (8 blocks) -----------------------------
    if (bk < 8) {
        int b = 4 + (bk >> 1);
        int tile0 = 128 + (b - 4) * 16;
        int c = (bk & 1) * 512 + t;
        if (t == 0) {
            float es = 0.f;
#pragma unroll
            for (int j = 0; j < 16; ++j) es += g_eblk[tile0 + j];
            s_scale = 1.f / es;
        }
        float acc = 0.f;
#pragma unroll
        for (int j = 0; j < 16; ++j)
            acc += g_vpart[(size_t)(tile0 + j) * CC + c];
        __syncthreads();
        g_vbar[b * CC + c] = acc * s_scale;
    }
    grid_barrier(bk, m0, 7);

    // ---- P3b: outs for batches 4-7 (64 blocks x 16 d) ---------------------
    if (bk < 64) {
        int d = bk * 16 + w;
        const float4* wp = (const float4*)(Wv + (size_t)d * CC);
        const float4* vb = (const float4*)g_vbar;
        float acc[4] = {0.f, 0.f, 0.f, 0.f};
#pragma unroll
        for (int i = 0; i < 8; ++i) {
            int idx = lane + i * 32;
            float4 wv = wp[idx];
#pragma unroll
            for (int b = 0; b < 4; ++b) {
                float4 v = vb[(4 + b) * 256 + idx];
                acc[b] += wv.x * v.x + wv.y * v.y + wv.z * v.z + wv.w * v.w;
            }
        }
#pragma unroll
        for (int b = 0; b < 4; ++b)
#pragma unroll
            for (int o = 16; o; o >>= 1)
                acc[b] += __shfl_xor_sync(0xFFFFFFFFu, acc[b], o);
        if (lane == 0) {
            float bias = bv[d];
#pragma unroll
            for (int b = 0; b < 4; ++b) g_outs[(4 + b) * CC + d] = acc[b] + bias;
        }
    }
    grid_barrier(bk, m0, 8);

    // ---- P4b: write batches 4-7 (32MB, all 148 blocks) --------------------
    p4_write(out, GRID, bk, 4, HALF4);
}

extern "C" void kernel_launch(void* const* d_in, const int* in_sizes, int n_in,
                              void* d_out, int out_size) {
    const float* key   = (const float*)d_in[1];
    const float* value = (const float*)d_in[2];
    const float* Wk    = (const float*)d_in[5];
    const float* Wv    = (const float*)d_in[7];
    const float* bv    = (const float*)d_in[8];
    const float* fckw  = (const float*)d_in[11];
    k_fused<<<GRID, TPB>>>(key, value, Wk, Wv, bv, fckw, (float4*)d_out);
}

// round 12
// speedup vs baseline: 1.2423x; 1.2423x over previous
#include <cuda_runtime.h>

// FeedForwardAttention — algebraically reduced, single persistent kernel.
//   attns[b,q,:] = softmax_k(u . key[b,k]),  u = Wk^T fck_w
//   out[b,q,:]   = Wv @ (sum_k e_k value[b,k,:]) / (sum_k e_k) + bv  (q-independent)
// Round-7 structure (best measured) + P4 rewritten as TMA bulk stores:
// outs staged in smem, cp.async.bulk shared->global, 4KB per output row.

#define BB 8
#define LL 2048
#define CC 1024
#define GRID 148
#define TPB 512
#define P0B 128
#define P1B 128

__device__ float g_upart[P0B * CC];
__device__ float g_u[CC];
__device__ float g_vpart[P1B * CC];
__device__ float g_eblk[P1B];
__device__ float g_vbar[BB * CC];
__device__ float g_outs[BB * CC];
__device__ unsigned g_count = 0;
__device__ unsigned g_gen = 0;

__device__ __forceinline__ void grid_barrier() {
    __syncthreads();
    if (threadIdx.x == 0) {
        unsigned gen = *(volatile unsigned*)&g_gen;
        __threadfence();
        if (atomicAdd(&g_count, 1u) == GRID - 1) {
            atomicExch(&g_count, 0u);
            __threadfence();
            atomicAdd(&g_gen, 1u);
        } else {
            while (*(volatile unsigned*)&g_gen == gen) { }
            __threadfence();
        }
    }
    __syncthreads();
}

__device__ __forceinline__ unsigned smem_u32(const void* p) {
    unsigned a;
    asm("{ .reg .u64 tmp; cvta.to.shared.u64 tmp, %1; cvt.u32.u64 %0, tmp; }"
        : "=r"(a) : "l"(p));
    return a;
}

__global__ void __launch_bounds__(TPB, 1) k_fused(
    const float* __restrict__ key, const float* __restrict__ value,
    const float* __restrict__ Wk, const float* __restrict__ Wv,
    const float* __restrict__ bv, const float* __restrict__ fckw,
    float4* __restrict__ out)
{
    __shared__ float4 su4[CC / 4];      // 4KB staged u
    __shared__ float4 sbuf[8][CC / 4];  // 32KB: P1 reduce, then P4 staging
    __shared__ float  sew[16];
    __shared__ float  s_scale;

    const int bk = blockIdx.x, t = threadIdx.x;
    const int w = t >> 5, lane = t & 31;

    // ---- P0: u partials (128 blocks x 8 o-rows; thread covers 2 cols) -----
    if (bk < P0B) {
        int o0 = bk * 8;
        float a0 = 0.f, a1 = 0.f;
#pragma unroll
        for (int o = 0; o < 8; ++o) {
            float f = fckw[o0 + o];
            const float* wr = Wk + (size_t)(o0 + o) * CC;
            a0 += f * wr[t];
            a1 += f * wr[t + 512];
        }
        g_upart[bk * CC + t]       = a0;
        g_upart[bk * CC + t + 512] = a1;
    }
    grid_barrier();

    // ---- P0b: u reduce (8 blocks x 128 columns) ---------------------------
    if (bk < 8 && t < 128) {
        int c = bk * 128 + t;
        float acc = 0.f;
#pragma unroll
        for (int j = 0; j < P0B; ++j) acc += g_upart[j * CC + c];
        g_u[c] = acc;
    }
    grid_barrier();

    // ---- P1: fused, warp-local, batched loads (128 blocks x 128 rows) -----
    if (bk < P1B) {
        if (t < 256) su4[t] = ((const float4*)g_u)[t];
        __syncthreads();
        const int b = bk >> 4;
        const int row0 = b * LL + (bk & 15) * 128;

        float4 acc[8];
#pragma unroll
        for (int i = 0; i < 8; ++i) acc[i] = make_float4(0.f, 0.f, 0.f, 0.f);
        float e_acc = 0.f;

#pragma unroll 2
        for (int it = 0; it < 8; ++it) {
            const int row = row0 + it * 16 + w;
            const float4* kr = (const float4*)key + (size_t)row * 256;
            const float4* vr = (const float4*)value + (size_t)row * 256;
            float4 kv[8], vv[8];
#pragma unroll
            for (int i = 0; i < 8; ++i) kv[i] = kr[lane + i * 32];
#pragma unroll
            for (int i = 0; i < 8; ++i) vv[i] = vr[lane + i * 32];
            float d = 0.f;
#pragma unroll
            for (int i = 0; i < 8; ++i) {
                float4 uv = su4[lane + i * 32];
                d += kv[i].x * uv.x + kv[i].y * uv.y + kv[i].z * uv.z + kv[i].w * uv.w;
            }
#pragma unroll
            for (int o = 16; o; o >>= 1) d += __shfl_xor_sync(0xFFFFFFFFu, d, o);
            const float e = __expf(d);
            e_acc += e;
#pragma unroll
            for (int i = 0; i < 8; ++i) {
                acc[i].x += e * vv[i].x; acc[i].y += e * vv[i].y;
                acc[i].z += e * vv[i].z; acc[i].w += e * vv[i].w;
            }
        }

        // reduce 16 warp partials -> 8 bufs -> 1
        if (w < 8) {
#pragma unroll
            for (int i = 0; i < 8; ++i) sbuf[w][lane + i * 32] = acc[i];
        }
        if (lane == 0) sew[w] = e_acc;
        __syncthreads();
        if (w >= 8) {
            int bf = w - 8;
#pragma unroll
            for (int i = 0; i < 8; ++i) {
                float4 c = sbuf[bf][lane + i * 32];
                c.x += acc[i].x; c.y += acc[i].y; c.z += acc[i].z; c.w += acc[i].w;
                sbuf[bf][lane + i * 32] = c;
            }
        }
        __syncthreads();
        if (t < 256) {
            float4 s = make_float4(0.f, 0.f, 0.f, 0.f);
#pragma unroll
            for (int j = 0; j < 8; ++j) {
                float4 c = sbuf[j][t];
                s.x += c.x; s.y += c.y; s.z += c.z; s.w += c.w;
            }
            ((float4*)g_vpart)[bk * 256 + t] = s;
        } else if (w == 8) {
            float s = (lane < 16) ? sew[lane] : 0.f;
#pragma unroll
            for (int o = 16; o; o >>= 1) s += __shfl_xor_sync(0xFFFFFFFFu, s, o);
            if (lane == 0) g_eblk[bk] = s;
        }
    }
    grid_barrier();

    // ---- P2: vbar[b][c] = sum_j vpart / esum[b]  (8 blocks) ---------------
    if (bk < BB) {
        if (t == 0) {
            float es = 0.f;
#pragma unroll
            for (int j = 0; j < 16; ++j) es += g_eblk[bk * 16 + j];
            s_scale = 1.f / es;
        }
        float a0 = 0.f, a1 = 0.f;
#pragma unroll
        for (int j = 0; j < 16; ++j) {
            const float* vp = g_vpart + (size_t)(bk * 16 + j) * CC;
            a0 += vp[t];
            a1 += vp[t + 512];
        }
        __syncthreads();
        g_vbar[bk * CC + t]       = a0 * s_scale;
        g_vbar[bk * CC + t + 512] = a1 * s_scale;
    }
    grid_barrier();

    // ---- P3: outs[b][d] = Wv[d] . vbar[b] + bv[d]  (64 blocks x 16 d) -----
    if (bk < 64) {
        int d = bk * 16 + w;
        const float4* wp = (const float4*)(Wv + (size_t)d * CC);
        const float4* vb = (const float4*)g_vbar;
        float acc[BB];
#pragma unroll
        for (int b = 0; b < BB; ++b) acc[b] = 0.f;
#pragma unroll
        for (int i = 0; i < 8; ++i) {
            int idx = lane + i * 32;
            float4 wv = wp[idx];
#pragma unroll
            for (int b = 0; b < BB; ++b) {
                float4 v = vb[b * 256 + idx];
                acc[b] += wv.x * v.x + wv.y * v.y + wv.z * v.z + wv.w * v.w;
            }
        }
#pragma unroll
        for (int b = 0; b < BB; ++b)
#pragma unroll
            for (int o = 16; o; o >>= 1)
                acc[b] += __shfl_xor_sync(0xFFFFFFFFu, acc[b], o);
        if (lane == 0) {
            float bias = bv[d];
#pragma unroll
            for (int b = 0; b < BB; ++b) g_outs[b * CC + d] = acc[b] + bias;
        }
    }
    grid_barrier();

    // ---- P4: broadcast via TMA bulk stores (64MB write) -------------------
    {
        // Stage all 8 outs rows (32KB) into smem (reusing sbuf).
        float* stage = (float*)sbuf;
#pragma unroll
        for (int i = 0; i < 16; ++i)
            stage[t + i * TPB] = g_outs[t + i * TPB];
        __syncthreads();
        asm volatile("fence.proxy.async.shared::cta;" ::: "memory");

        // Each warp's lane 0 issues 4KB bulk stores: one per output row.
        // Rows r = bk + GRID*(w + 16*j); batch = r >> 11.
        if (lane == 0) {
            const unsigned sbase = smem_u32(stage);
            float* outf = (float*)out;
            for (int r = bk + GRID * w; r < BB * LL; r += GRID * 16) {
                const unsigned src = sbase + (unsigned)(r >> 11) * 4096u;
                float* dst = outf + (size_t)r * CC;
                asm volatile(
                    "cp.async.bulk.global.shared::cta.bulk_group [%0], [%1], %2;"
                    :: "l"(dst), "r"(src), "r"(4096) : "memory");
            }
            asm volatile("cp.async.bulk.commit_group;" ::: "memory");
            asm volatile("cp.async.bulk.wait_group 0;" ::: "memory");
        }
        __syncthreads();
    }
}

extern "C" void kernel_launch(void* const* d_in, const int* in_sizes, int n_in,
                              void* d_out, int out_size) {
    const float* key   = (const float*)d_in[1];
    const float* value = (const float*)d_in[2];
    const float* Wk    = (const float*)d_in[5];
    const float* Wv    = (const float*)d_in[7];
    const float* bv    = (const float*)d_in[8];
    const float* fckw  = (const float*)d_in[11];
    k_fused<<<GRID, TPB>>>(key, value, Wk, Wv, bv, fckw, (float4*)d_out);
}

// round 13
// speedup vs baseline: 1.2582x; 1.0128x over previous
#include <cuda_runtime.h>

// FeedForwardAttention — algebraically reduced, single persistent kernel.
//   attns[b,q,:] = softmax_k(u . key[b,k]),  u = Wk^T fck_w
//   out[b,q,:]   = Wv @ (sum_k e_k value[b,k,:]) / (sum_k e_k) + bv  (q-independent)
// 1024 thr/block (32 warps/SM), every phase <=64 regs (no spills):
//   P1a dots (warp/row), P1b value accumulate (warp/half-row), both in-block.
// Streaming cache hints: __ldcs on key/value, __stcs on output.

#define BB 8
#define LL 2048
#define CC 1024
#define GRID 148
#define TPB 1024
#define P0B 128
#define P1B 128

__device__ float g_upart[P0B * CC];
__device__ float g_u[CC];
__device__ float g_vpart[P1B * CC];
__device__ float g_eblk[P1B];
__device__ float g_vbar[BB * CC];
__device__ float g_outs[BB * CC];
__device__ unsigned g_count = 0;
__device__ unsigned g_gen = 0;

__device__ __forceinline__ void grid_barrier() {
    __syncthreads();
    if (threadIdx.x == 0) {
        unsigned gen = *(volatile unsigned*)&g_gen;
        __threadfence();
        if (atomicAdd(&g_count, 1u) == GRID - 1) {
            atomicExch(&g_count, 0u);
            __threadfence();
            atomicAdd(&g_gen, 1u);
        } else {
            while (*(volatile unsigned*)&g_gen == gen) { }
            __threadfence();
        }
    }
    __syncthreads();
}

__global__ void __launch_bounds__(TPB, 1) k_fused(
    const float* __restrict__ key, const float* __restrict__ value,
    const float* __restrict__ Wk, const float* __restrict__ Wv,
    const float* __restrict__ bv, const float* __restrict__ fckw,
    float4* __restrict__ out)
{
    __shared__ float4 su4[CC / 4];      // 4KB staged u
    __shared__ float4 sbuf[8][CC / 4];  // 32KB warp-partial reduce
    __shared__ float  se[128];          // per-row e within block
    __shared__ float  sew[32];
    __shared__ float  s_scale;

    const int bk = blockIdx.x, t = threadIdx.x;
    const int w = t >> 5, lane = t & 31;

    // ---- P0: u partials (128 blocks x 8 o-rows x 1024 cols) ---------------
    if (bk < P0B) {
        int o0 = bk * 8;
        float a0 = 0.f;
#pragma unroll
        for (int o = 0; o < 8; ++o)
            a0 += fckw[o0 + o] * Wk[(size_t)(o0 + o) * CC + t];
        g_upart[bk * CC + t] = a0;
    }
    grid_barrier();

    // ---- P0b: u reduce (8 blocks x 128 columns) ---------------------------
    if (bk < 8 && t < 128) {
        int c = bk * 128 + t;
        float acc = 0.f;
#pragma unroll
        for (int j = 0; j < P0B; ++j) acc += g_upart[j * CC + c];
        g_u[c] = acc;
    }
    grid_barrier();

    // ---- P1: fused block pass over 128 rows (128 blocks) ------------------
    if (bk < P1B) {
        if (t < 256) su4[t] = ((const float4*)g_u)[t];
        __syncthreads();
        const int row0 = bk * 128;      // global row; batch = bk >> 4

        // -- P1a: dots. warp w rows row0 + it*32 + w (4 rows/warp) ----------
        {
            float e_acc = 0.f;
#pragma unroll
            for (int it = 0; it < 4; ++it) {
                const int row = row0 + it * 32 + w;
                const float4* kr = (const float4*)key + (size_t)row * 256;
                float4 kv[8];
#pragma unroll
                for (int i = 0; i < 8; ++i) kv[i] = __ldcs(kr + lane + i * 32);
                float d = 0.f;
#pragma unroll
                for (int i = 0; i < 8; ++i) {
                    float4 uv = su4[lane + i * 32];
                    d += kv[i].x * uv.x + kv[i].y * uv.y + kv[i].z * uv.z + kv[i].w * uv.w;
                }
#pragma unroll
                for (int o = 16; o; o >>= 1) d += __shfl_xor_sync(0xFFFFFFFFu, d, o);
                const float e = __expf(d);
                e_acc += e;
                if (lane == 0) se[it * 32 + w] = e;
            }
            if (lane == 0) sew[w] = e_acc;
        }
        __syncthreads();

        // -- P1b: value. warp w = (group g=w>>1, half h=w&1); 8 rows/warp ---
        {
            const int g = w >> 1, h = w & 1;
            const int cbase = h * 128 + lane;   // float4 column base
            float4 acc[4];
#pragma unroll
            for (int i = 0; i < 4; ++i) acc[i] = make_float4(0.f, 0.f, 0.f, 0.f);
#pragma unroll 2
            for (int it = 0; it < 8; ++it) {
                const int r = it * 16 + g;
                const float4* vr = (const float4*)value + (size_t)(row0 + r) * 256;
                float4 vv[4];
#pragma unroll
                for (int i = 0; i < 4; ++i) vv[i] = __ldcs(vr + cbase + i * 32);
                const float e = se[r];
#pragma unroll
                for (int i = 0; i < 4; ++i) {
                    acc[i].x += e * vv[i].x; acc[i].y += e * vv[i].y;
                    acc[i].z += e * vv[i].z; acc[i].w += e * vv[i].w;
                }
            }
            // reduce: 16 warps per half -> 8 bufs (w<16 write, w>=16 add)
            if (w < 16) {
#pragma unroll
                for (int i = 0; i < 4; ++i) sbuf[g][cbase + i * 32] = acc[i];
            }
            __syncthreads();
            if (w >= 16) {
                int bf = g - 8;
#pragma unroll
                for (int i = 0; i < 4; ++i) {
                    float4 c = sbuf[bf][cbase + i * 32];
                    c.x += acc[i].x; c.y += acc[i].y; c.z += acc[i].z; c.w += acc[i].w;
                    sbuf[bf][cbase + i * 32] = c;
                }
            }
            __syncthreads();
            if (t < 256) {
                float4 s = make_float4(0.f, 0.f, 0.f, 0.f);
#pragma unroll
                for (int j = 0; j < 8; ++j) {
                    float4 c = sbuf[j][t];
                    s.x += c.x; s.y += c.y; s.z += c.z; s.w += c.w;
                }
                ((float4*)g_vpart)[bk * 256 + t] = s;
            } else if (w == 8) {
                float s = sew[lane];
#pragma unroll
                for (int o = 16; o; o >>= 1) s += __shfl_xor_sync(0xFFFFFFFFu, s, o);
                if (lane == 0) g_eblk[bk] = s;
            }
        }
    }
    grid_barrier();

    // ---- P2: vbar[b][c] = sum_j vpart / esum[b]  (8 blocks x 1024 cols) ---
    if (bk < BB) {
        if (t == 0) {
            float es = 0.f;
#pragma unroll
            for (int j = 0; j < 16; ++j) es += g_eblk[bk * 16 + j];
            s_scale = 1.f / es;
        }
        float a0 = 0.f;
#pragma unroll
        for (int j = 0; j < 16; ++j)
            a0 += g_vpart[(size_t)(bk * 16 + j) * CC + t];
        __syncthreads();
        g_vbar[bk * CC + t] = a0 * s_scale;
    }
    grid_barrier();

    // ---- P3: outs[b][d] = Wv[d] . vbar[b] + bv[d]  (32 blocks x 32 d) -----
    if (bk < 32) {
        int d = bk * 32 + w;
        const float4* wp = (const float4*)(Wv + (size_t)d * CC);
        const float4* vb = (const float4*)g_vbar;
        float acc[BB];
#pragma unroll
        for (int b = 0; b < BB; ++b) acc[b] = 0.f;
#pragma unroll
        for (int i = 0; i < 8; ++i) {
            int idx = lane + i * 32;
            float4 wv = wp[idx];
#pragma unroll
            for (int b = 0; b < BB; ++b) {
                float4 v = vb[b * 256 + idx];
                acc[b] += wv.x * v.x + wv.y * v.y + wv.z * v.z + wv.w * v.w;
            }
        }
#pragma unroll
        for (int b = 0; b < BB; ++b)
#pragma unroll
            for (int o = 16; o; o >>= 1)
                acc[b] += __shfl_xor_sync(0xFFFFFFFFu, acc[b], o);
        if (lane == 0) {
            float bias = bv[d];
#pragma unroll
            for (int b = 0; b < BB; ++b) g_outs[b * CC + d] = acc[b] + bias;
        }
    }
    grid_barrier();

    // ---- P4: broadcast outs[b,:] to all q rows (64MB streaming write) -----
    {
        const int i0 = bk * TPB + t;
        const int d4 = i0 & 255;        // fixed: stride is multiple of 256
        const float4* os = (const float4*)g_outs;
        float4 r0 = os[0 * 256 + d4], r1 = os[1 * 256 + d4];
        float4 r2 = os[2 * 256 + d4], r3 = os[3 * 256 + d4];
        float4 r4 = os[4 * 256 + d4], r5 = os[5 * 256 + d4];
        float4 r6 = os[6 * 256 + d4], r7 = os[7 * 256 + d4];
        const int total4 = BB * LL * CC / 4;
        for (int i = i0; i < total4; i += GRID * TPB) {
            int b = i >> 19;
            float4 r = (b < 4) ? ((b < 2) ? (b == 0 ? r0 : r1) : (b == 2 ? r2 : r3))
                               : ((b < 6) ? (b == 4 ? r4 : r5) : (b == 6 ? r6 : r7));
            __stcs(out + i, r);
        }
    }
}

extern "C" void kernel_launch(void* const* d_in, const int* in_sizes, int n_in,
                              void* d_out, int out_size) {
    const float* key   = (const float*)d_in[1];
    const float* value = (const float*)d_in[2];
    const float* Wk    = (const float*)d_in[5];
    const float* Wv    = (const float*)d_in[7];
    const float* bv    = (const float*)d_in[8];
    const float* fckw  = (const float*)d_in[11];
    k_fused<<<GRID, TPB>>>(key, value, Wk, Wv, bv, fckw, (float4*)d_out);
}